// round 4
// baseline (speedup 1.0000x reference)
#include <cuda_runtime.h>
#include <cuda_fp16.h>
#include <math.h>

#define N0 8192
#define N1 4096
#define N2 8192
// W0: [N0, N1] row-major, W1: [N1, N2] row-major

// Persistent state (device globals — allocation-free scratch)
__device__ float g_x1[N1];
__device__ float g_x2[N2];
__device__ float g_e1[N1];
__device__ float g_g1[N1];
__device__ float g_g2[N2];
__device__ __half g_x2h[N2];
__device__ int   g_ctr;
// fp16 weight copies (written once in step 1, read in steps 2..9 + final)
__device__ __half g_W0h[(size_t)N0 * N1];   // 64 MB
__device__ __half g_W1h[(size_t)N1 * N2];   // 64 MB

__device__ __forceinline__ float dot4(float4 a, float4 b) {
    return a.x * b.x + a.y * b.y + a.z * b.z + a.w * b.w;
}
// dot of 8 halfs (uint4) with 8 floats
__device__ __forceinline__ float dot8_hf(uint4 w, const float* x) {
    const __half2* h = (const __half2*)&w;
    float s = 0.f;
#pragma unroll
    for (int j = 0; j < 4; j++) {
        float2 f = __half22float2(h[j]);
        s += f.x * x[2 * j] + f.y * x[2 * j + 1];
    }
    return s;
}
// dot of 8 halfs with 8 halfs, fp32 accumulate
__device__ __forceinline__ float dot8_hh(uint4 w, uint4 xh) {
    const __half2* hw = (const __half2*)&w;
    const __half2* hx = (const __half2*)&xh;
    float s = 0.f;
#pragma unroll
    for (int j = 0; j < 4; j++) {
        float2 fw = __half22float2(hw[j]);
        float2 fx = __half22float2(hx[j]);
        s += fw.x * fx.x + fw.y * fx.y;
    }
    return s;
}
// a[0..8) += e * w (8 halfs)
__device__ __forceinline__ void axpy8_h(uint4 w, float e, float* a) {
    const __half2* h = (const __half2*)&w;
#pragma unroll
    for (int j = 0; j < 4; j++) {
        float2 f = __half22float2(h[j]);
        a[2 * j]     += e * f.x;
        a[2 * j + 1] += e * f.y;
    }
}
__device__ __forceinline__ uint2 f4_to_h4(float4 v) {
    __half2 a = __floats2half2_rn(v.x, v.y);
    __half2 b = __floats2half2_rn(v.z, v.w);
    uint2 u;
    u.x = *(unsigned*)&a;
    u.y = *(unsigned*)&b;
    return u;
}

// ---------------------------------------------------------------------------
__global__ void k_init(float* __restrict__ out) {
    int i = blockIdx.x * blockDim.x + threadIdx.x;
    if (i < N1) { g_x1[i] = 0.f; g_g1[i] = 0.f; g_e1[i] = 0.f; }
    if (i < N2) { g_x2[i] = 0.f; g_g2[i] = 0.f; g_x2h[i] = __float2half(0.f); }
    if (i == 0) { out[0] = 0.f; g_ctr = 0; }
}

// ---------------------------------------------------------------------------
// Fused state update, executed by the LAST block of a step kernel
// (threadfence-reduction pattern). Also zeroes grads + resets counter.
// ---------------------------------------------------------------------------
__device__ __forceinline__ void step_epilogue(int nblocks) {
    __shared__ int is_last;
    __threadfence();
    if (threadIdx.x == 0) {
        int v = atomicAdd(&g_ctr, 1);
        is_last = (v == nblocks - 1);
    }
    __syncthreads();
    if (!is_last) return;
    __threadfence();   // acquire: order following loads after observing all arrivals
    const int tid = threadIdx.x;
    const int nt  = blockDim.x;
    for (int i = tid; i < N1; i += nt) {
        float gr = fminf(fmaxf(-g_e1[i] + g_g1[i], -1.f), 1.f);
        g_x1[i] = tanhf(g_x1[i] + 0.01f * gr);
        g_g1[i] = 0.f;
    }
    for (int i = tid; i < N2; i += nt) {
        float x2 = g_x2[i];
        float gr = fminf(fmaxf(-x2 + g_g2[i], -1.f), 1.f);
        float nx = tanhf(x2 + 0.01f * gr);
        g_x2[i]  = nx;
        g_x2h[i] = __float2half(nx);
        g_g2[i]  = 0.f;
    }
    if (tid == 0) g_ctr = 0;
}

// ---------------------------------------------------------------------------
// Step 1: fp32 fused step (register-tiled, W read ONCE) + writes fp16 copies
// of W0/W1 + fused update epilogue.
// Blocks [0,128): W0 (64 rows). Blocks [128,256): W1 (32 rows). 512 threads.
// ---------------------------------------------------------------------------
__global__ void __launch_bounds__(512) k_step1(const float* __restrict__ x0,
                                               const float* __restrict__ W0,
                                               const float* __restrict__ W1) {
    __shared__ float sp[8][16];
    __shared__ float se[8];
    const int tid  = threadIdx.x;
    const int warp = tid >> 5;
    const int lane = tid & 31;

    if (blockIdx.x < 128) {
        const int rowBase = blockIdx.x * 64;
        const float4* xv = (const float4*)g_x1;
        const float4 xA = xv[tid];
        const float4 xB = xv[tid + 512];
        float4 accA = make_float4(0, 0, 0, 0);
        float4 accB = make_float4(0, 0, 0, 0);

        #pragma unroll 1
        for (int t = 0; t < 8; t++) {
            const int rb = rowBase + t * 8;
            const float4* base = (const float4*)W0 + (size_t)rb * 1024 + tid;
            float4 wA[8], wB[8];
            #pragma unroll
            for (int r = 0; r < 8; r++) {
                wA[r] = base[(size_t)r * 1024];
                wB[r] = base[(size_t)r * 1024 + 512];
            }
            // half copies
            #pragma unroll
            for (int r = 0; r < 8; r++) {
                uint2* dst = (uint2*)g_W0h + (size_t)(rb + r) * 1024;
                dst[tid]       = f4_to_h4(wA[r]);
                dst[tid + 512] = f4_to_h4(wB[r]);
            }
            #pragma unroll
            for (int r = 0; r < 8; r++) {
                float p = dot4(wA[r], xA) + dot4(wB[r], xB);
                #pragma unroll
                for (int o = 16; o; o >>= 1) p += __shfl_xor_sync(0xFFFFFFFFu, p, o);
                if (lane == 0) sp[r][warp] = p;
            }
            __syncthreads();
            if (tid < 8) {
                float s = 0.f;
                #pragma unroll
                for (int w = 0; w < 16; w++) s += sp[tid][w];
                se[tid] = x0[rb + tid] - tanhf(s);
            }
            __syncthreads();
            #pragma unroll
            for (int r = 0; r < 8; r++) {
                const float e = se[r];
                accA.x += e * wA[r].x;  accA.y += e * wA[r].y;
                accA.z += e * wA[r].z;  accA.w += e * wA[r].w;
                accB.x += e * wB[r].x;  accB.y += e * wB[r].y;
                accB.z += e * wB[r].z;  accB.w += e * wB[r].w;
            }
        }
        const int cA = 4 * tid;
        const int cB = 4 * (tid + 512);
        atomicAdd(&g_g1[cA + 0], accA.x);
        atomicAdd(&g_g1[cA + 1], accA.y);
        atomicAdd(&g_g1[cA + 2], accA.z);
        atomicAdd(&g_g1[cA + 3], accA.w);
        atomicAdd(&g_g1[cB + 0], accB.x);
        atomicAdd(&g_g1[cB + 1], accB.y);
        atomicAdd(&g_g1[cB + 2], accB.z);
        atomicAdd(&g_g1[cB + 3], accB.w);
    } else {
        const int rowBase = (blockIdx.x - 128) * 32;
        const float4* xv = (const float4*)g_x2;
        float4 xC[4];
        #pragma unroll
        for (int k = 0; k < 4; k++) xC[k] = xv[tid + k * 512];
        float4 acc[4] = {make_float4(0,0,0,0), make_float4(0,0,0,0),
                         make_float4(0,0,0,0), make_float4(0,0,0,0)};

        #pragma unroll 1
        for (int t = 0; t < 8; t++) {
            const int rb = rowBase + t * 4;
            const float4* base = (const float4*)W1 + (size_t)rb * 2048 + tid;
            float4 w[4][4];
            #pragma unroll
            for (int r = 0; r < 4; r++)
                #pragma unroll
                for (int k = 0; k < 4; k++)
                    w[r][k] = base[(size_t)r * 2048 + k * 512];
            // half copies
            #pragma unroll
            for (int r = 0; r < 4; r++) {
                uint2* dst = (uint2*)g_W1h + (size_t)(rb + r) * 2048;
                #pragma unroll
                for (int k = 0; k < 4; k++)
                    dst[tid + k * 512] = f4_to_h4(w[r][k]);
            }
            #pragma unroll
            for (int r = 0; r < 4; r++) {
                float p = dot4(w[r][0], xC[0]) + dot4(w[r][1], xC[1])
                        + dot4(w[r][2], xC[2]) + dot4(w[r][3], xC[3]);
                #pragma unroll
                for (int o = 16; o; o >>= 1) p += __shfl_xor_sync(0xFFFFFFFFu, p, o);
                if (lane == 0) sp[r][warp] = p;
            }
            __syncthreads();
            if (tid < 4) {
                float s = 0.f;
                #pragma unroll
                for (int wi = 0; wi < 16; wi++) s += sp[tid][wi];
                float e = g_x1[rb + tid] - tanhf(s);
                se[tid] = e;
                g_e1[rb + tid] = e;
            }
            __syncthreads();
            #pragma unroll
            for (int r = 0; r < 4; r++) {
                const float e = se[r];
                #pragma unroll
                for (int k = 0; k < 4; k++) {
                    acc[k].x += e * w[r][k].x;  acc[k].y += e * w[r][k].y;
                    acc[k].z += e * w[r][k].z;  acc[k].w += e * w[r][k].w;
                }
            }
        }
        #pragma unroll
        for (int k = 0; k < 4; k++) {
            const int c = 4 * (tid + k * 512);
            atomicAdd(&g_g2[c + 0], acc[k].x);
            atomicAdd(&g_g2[c + 1], acc[k].y);
            atomicAdd(&g_g2[c + 2], acc[k].z);
            atomicAdd(&g_g2[c + 3], acc[k].w);
        }
    }
    step_epilogue(256);
}

// ---------------------------------------------------------------------------
// Steps 2..9: fp16 fused step. 256 threads, 2 blocks/SM.
// Blocks [0,128): W1 (32 rows each, 1 MB — scheduled first).
// Blocks [128,384): W0 (32 rows each, 0.5 MB).
// ---------------------------------------------------------------------------
__global__ void __launch_bounds__(256, 2) k_step_h(const float* __restrict__ x0) {
    __shared__ float sp[8][8];
    __shared__ float se[8];
    const int tid  = threadIdx.x;
    const int warp = tid >> 5;
    const int lane = tid & 31;

    if (blockIdx.x >= 128) {
        // ---------------- W0h: [8192 x 4096] halfs, row = 512 uint4 --------
        const int rowBase = (blockIdx.x - 128) * 32;
        const uint4* W = (const uint4*)g_W0h;
        float xf[16];
        {
            const float4* xv = (const float4*)g_x1;
            float4 a = xv[2 * tid],           b = xv[2 * tid + 1];
            float4 c = xv[2 * (tid + 256)],   d = xv[2 * (tid + 256) + 1];
            xf[0]=a.x; xf[1]=a.y; xf[2]=a.z; xf[3]=a.w;
            xf[4]=b.x; xf[5]=b.y; xf[6]=b.z; xf[7]=b.w;
            xf[8]=c.x; xf[9]=c.y; xf[10]=c.z; xf[11]=c.w;
            xf[12]=d.x; xf[13]=d.y; xf[14]=d.z; xf[15]=d.w;
        }
        float acc[16];
        #pragma unroll
        for (int j = 0; j < 16; j++) acc[j] = 0.f;

        #pragma unroll 1
        for (int t = 0; t < 4; t++) {
            const int rb = rowBase + t * 8;
            uint4 w0[8], w1[8];
            #pragma unroll
            for (int r = 0; r < 8; r++) {
                w0[r] = W[(size_t)(rb + r) * 512 + tid];
                w1[r] = W[(size_t)(rb + r) * 512 + tid + 256];
            }
            #pragma unroll
            for (int r = 0; r < 8; r++) {
                float p = dot8_hf(w0[r], xf) + dot8_hf(w1[r], xf + 8);
                #pragma unroll
                for (int o = 16; o; o >>= 1) p += __shfl_xor_sync(0xFFFFFFFFu, p, o);
                if (lane == 0) sp[r][warp] = p;
            }
            __syncthreads();
            if (tid < 64) {
                int r = tid >> 3, wi = tid & 7;
                float v = sp[r][wi];
                v += __shfl_xor_sync(0xFFFFFFFFu, v, 4);
                v += __shfl_xor_sync(0xFFFFFFFFu, v, 2);
                v += __shfl_xor_sync(0xFFFFFFFFu, v, 1);
                if (wi == 0) se[r] = x0[rb + r] - tanhf(v);
            }
            __syncthreads();
            #pragma unroll
            for (int r = 0; r < 8; r++) {
                const float e = se[r];
                axpy8_h(w0[r], e, acc);
                axpy8_h(w1[r], e, acc + 8);
            }
        }
        #pragma unroll
        for (int j = 0; j < 8; j++) atomicAdd(&g_g1[8 * tid + j], acc[j]);
        #pragma unroll
        for (int j = 0; j < 8; j++) atomicAdd(&g_g1[8 * (tid + 256) + j], acc[8 + j]);
    } else {
        // ---------------- W1h: [4096 x 8192] halfs, row = 1024 uint4 -------
        const int rowBase = blockIdx.x * 32;
        const uint4* W = (const uint4*)g_W1h;
        const uint4* X2 = (const uint4*)g_x2h;
        uint4 xh[4];
        #pragma unroll
        for (int k = 0; k < 4; k++) xh[k] = X2[tid + 256 * k];
        float acc[32];
        #pragma unroll
        for (int j = 0; j < 32; j++) acc[j] = 0.f;

        #pragma unroll 1
        for (int t = 0; t < 8; t++) {
            const int rb = rowBase + t * 4;
            uint4 w[4][4];
            #pragma unroll
            for (int r = 0; r < 4; r++)
                #pragma unroll
                for (int k = 0; k < 4; k++)
                    w[r][k] = W[(size_t)(rb + r) * 1024 + tid + 256 * k];
            #pragma unroll
            for (int r = 0; r < 4; r++) {
                float p = dot8_hh(w[r][0], xh[0]) + dot8_hh(w[r][1], xh[1])
                        + dot8_hh(w[r][2], xh[2]) + dot8_hh(w[r][3], xh[3]);
                #pragma unroll
                for (int o = 16; o; o >>= 1) p += __shfl_xor_sync(0xFFFFFFFFu, p, o);
                if (lane == 0) sp[r][warp] = p;
            }
            __syncthreads();
            if (tid < 32) {
                int r = tid >> 3, wi = tid & 7;
                float v = sp[r][wi];
                v += __shfl_xor_sync(0xFFFFFFFFu, v, 4);
                v += __shfl_xor_sync(0xFFFFFFFFu, v, 2);
                v += __shfl_xor_sync(0xFFFFFFFFu, v, 1);
                if (wi == 0) {
                    float e = g_x1[rb + r] - tanhf(v);
                    se[r] = e;
                    g_e1[rb + r] = e;
                }
            }
            __syncthreads();
            #pragma unroll
            for (int r = 0; r < 4; r++) {
                const float e = se[r];
                #pragma unroll
                for (int k = 0; k < 4; k++)
                    axpy8_h(w[r][k], e, acc + 8 * k);
            }
        }
        #pragma unroll
        for (int k = 0; k < 4; k++)
            #pragma unroll
            for (int j = 0; j < 8; j++)
                atomicAdd(&g_g2[8 * (tid + 256 * k) + j], acc[8 * k + j]);
    }
    step_epilogue(384);
}

// ---------------------------------------------------------------------------
// Final: err = ||x0 - tanh(W0@x1)||^2 + ||x1 - tanh(W1@x2)||^2 + ||x2||^2
// fp16 weights, warp-per-row.
// ---------------------------------------------------------------------------
__global__ void __launch_bounds__(256) k_final_h(const float* __restrict__ x0,
                                                 float* __restrict__ out) {
    __shared__ float s_part[8];
    const int warpInBlock = threadIdx.x >> 5;
    const int warp = (blockIdx.x * blockDim.x + threadIdx.x) >> 5;
    const int lane = threadIdx.x & 31;

    float local = 0.f;
    if (warp < N0) {
        const uint4* row = (const uint4*)g_W0h + (size_t)warp * 512;
        const float4* xv = (const float4*)g_x1;
        float acc = 0.f;
        #pragma unroll 4
        for (int i = lane; i < 512; i += 32) {
            uint4 w = row[i];
            float4 a = xv[2 * i], b = xv[2 * i + 1];
            float xf[8] = {a.x, a.y, a.z, a.w, b.x, b.y, b.z, b.w};
            acc += dot8_hf(w, xf);
        }
        #pragma unroll
        for (int o = 16; o; o >>= 1) acc += __shfl_xor_sync(0xFFFFFFFFu, acc, o);
        if (lane == 0) {
            float e = x0[warp] - tanhf(acc);
            float x2v = g_x2[warp];
            local = e * e + x2v * x2v;
        }
    } else {
        const int r = warp - N0;
        const uint4* row = (const uint4*)g_W1h + (size_t)r * 1024;
        const uint4* X2 = (const uint4*)g_x2h;
        float acc = 0.f;
        #pragma unroll 4
        for (int i = lane; i < 1024; i += 32)
            acc += dot8_hh(row[i], X2[i]);
        #pragma unroll
        for (int o = 16; o; o >>= 1) acc += __shfl_xor_sync(0xFFFFFFFFu, acc, o);
        if (lane == 0) {
            float e = g_x1[r] - tanhf(acc);
            local = e * e;
        }
    }

    if (lane == 0) s_part[warpInBlock] = local;
    __syncthreads();
    if (threadIdx.x == 0) {
        float s = 0.f;
        #pragma unroll
        for (int w = 0; w < 8; w++) s += s_part[w];
        atomicAdd(out, s);
    }
}

// ---------------------------------------------------------------------------
extern "C" void kernel_launch(void* const* d_in, const int* in_sizes, int n_in,
                              void* d_out, int out_size) {
    const float* x0 = (const float*)d_in[0];
    const float* W0 = (const float*)d_in[1];
    const float* W1 = (const float*)d_in[2];
    float* out = (float*)d_out;

    k_init<<<32, 256>>>(out);
    k_step1<<<256, 512>>>(x0, W0, W1);          // fp32 step + fp16 conversion
    for (int s = 0; s < 8; s++)
        k_step_h<<<384, 256>>>(x0);             // fp16 steps 2..9
    k_final_h<<<(N0 + N1) / 8, 256>>>(x0, out); // fp16 final error
}

// round 5
// speedup vs baseline: 1.1531x; 1.1531x over previous
#include <cuda_runtime.h>
#include <cuda_fp16.h>
#include <math.h>

#define N0 8192
#define N1 4096
#define N2 8192
// W0: [N0, N1] row-major, W1: [N1, N2] row-major

// Persistent state (device globals — allocation-free scratch)
__device__ float g_x1[N1];
__device__ float g_x2[N2];
__device__ float g_e1[N1];
__device__ float g_g1[N1];
__device__ float g_g2[N2];
__device__ __half g_x1h[N1];
__device__ __half g_x2h[N2];
__device__ int   g_ctr;
// fp16 weight copies (written once in step 1, read in steps 2..9 + final)
__device__ __half g_W0h[(size_t)N0 * N1];   // 64 MB
__device__ __half g_W1h[(size_t)N1 * N2];   // 64 MB

__device__ __forceinline__ float dot4(float4 a, float4 b) {
    return a.x * b.x + a.y * b.y + a.z * b.z + a.w * b.w;
}
// convert 8 halfs (uint4) to 8 floats
__device__ __forceinline__ void h8_to_f8(uint4 w, float* f) {
    const __half2* h = (const __half2*)&w;
#pragma unroll
    for (int j = 0; j < 4; j++) {
        float2 v = __half22float2(h[j]);
        f[2 * j] = v.x;
        f[2 * j + 1] = v.y;
    }
}
__device__ __forceinline__ uint2 f4_to_h4(float4 v) {
    __half2 a = __floats2half2_rn(v.x, v.y);
    __half2 b = __floats2half2_rn(v.z, v.w);
    uint2 u;
    u.x = *(unsigned*)&a;
    u.y = *(unsigned*)&b;
    return u;
}

// ---------------------------------------------------------------------------
__global__ void k_init(float* __restrict__ out) {
    int i = blockIdx.x * blockDim.x + threadIdx.x;
    if (i < N1) { g_x1[i] = 0.f; g_g1[i] = 0.f; g_e1[i] = 0.f; g_x1h[i] = __float2half(0.f); }
    if (i < N2) { g_x2[i] = 0.f; g_g2[i] = 0.f; g_x2h[i] = __float2half(0.f); }
    if (i == 0) { out[0] = 0.f; g_ctr = 0; }
}

// ---------------------------------------------------------------------------
// Fused state update by the LAST block (threadfence-reduction pattern).
// Zeroes grads, maintains fp16 x copies, resets counter.
// ---------------------------------------------------------------------------
__device__ __forceinline__ void step_epilogue(int nblocks) {
    __shared__ int is_last;
    __threadfence();
    if (threadIdx.x == 0) {
        int v = atomicAdd(&g_ctr, 1);
        is_last = (v == nblocks - 1);
    }
    __syncthreads();
    if (!is_last) return;
    __threadfence();
    const int tid = threadIdx.x;
    const int nt  = blockDim.x;
    for (int i = tid; i < N1; i += nt) {
        float gr = fminf(fmaxf(-g_e1[i] + g_g1[i], -1.f), 1.f);
        float nx = tanhf(g_x1[i] + 0.01f * gr);
        g_x1[i]  = nx;
        g_x1h[i] = __float2half(nx);
        g_g1[i]  = 0.f;
    }
    for (int i = tid; i < N2; i += nt) {
        float x2 = g_x2[i];
        float gr = fminf(fmaxf(-x2 + g_g2[i], -1.f), 1.f);
        float nx = tanhf(x2 + 0.01f * gr);
        g_x2[i]  = nx;
        g_x2h[i] = __float2half(nx);
        g_g2[i]  = 0.f;
    }
    if (tid == 0) g_ctr = 0;
}

// ---------------------------------------------------------------------------
// Step 1: fp32 fused step (W read once) + write fp16 copies + fused update.
// Blocks [0,128): W0 (64 rows). Blocks [128,256): W1 (32 rows). 512 threads.
// ---------------------------------------------------------------------------
__global__ void __launch_bounds__(512) k_step1(const float* __restrict__ x0,
                                               const float* __restrict__ W0,
                                               const float* __restrict__ W1) {
    __shared__ float sp[8][16];
    __shared__ float se[8];
    const int tid  = threadIdx.x;
    const int warp = tid >> 5;
    const int lane = tid & 31;

    if (blockIdx.x < 128) {
        const int rowBase = blockIdx.x * 64;
        const float4* xv = (const float4*)g_x1;
        const float4 xA = xv[tid];
        const float4 xB = xv[tid + 512];
        float4 accA = make_float4(0, 0, 0, 0);
        float4 accB = make_float4(0, 0, 0, 0);

        #pragma unroll 1
        for (int t = 0; t < 8; t++) {
            const int rb = rowBase + t * 8;
            const float4* base = (const float4*)W0 + (size_t)rb * 1024 + tid;
            float4 wA[8], wB[8];
            #pragma unroll
            for (int r = 0; r < 8; r++) {
                wA[r] = base[(size_t)r * 1024];
                wB[r] = base[(size_t)r * 1024 + 512];
            }
            #pragma unroll
            for (int r = 0; r < 8; r++) {
                uint2* dst = (uint2*)g_W0h + (size_t)(rb + r) * 1024;
                dst[tid]       = f4_to_h4(wA[r]);
                dst[tid + 512] = f4_to_h4(wB[r]);
            }
            #pragma unroll
            for (int r = 0; r < 8; r++) {
                float p = dot4(wA[r], xA) + dot4(wB[r], xB);
                #pragma unroll
                for (int o = 16; o; o >>= 1) p += __shfl_xor_sync(0xFFFFFFFFu, p, o);
                if (lane == 0) sp[r][warp] = p;
            }
            __syncthreads();
            if (tid < 8) {
                float s = 0.f;
                #pragma unroll
                for (int w = 0; w < 16; w++) s += sp[tid][w];
                se[tid] = x0[rb + tid] - tanhf(s);
            }
            __syncthreads();
            #pragma unroll
            for (int r = 0; r < 8; r++) {
                const float e = se[r];
                accA.x += e * wA[r].x;  accA.y += e * wA[r].y;
                accA.z += e * wA[r].z;  accA.w += e * wA[r].w;
                accB.x += e * wB[r].x;  accB.y += e * wB[r].y;
                accB.z += e * wB[r].z;  accB.w += e * wB[r].w;
            }
        }
        const int cA = 4 * tid;
        const int cB = 4 * (tid + 512);
        atomicAdd(&g_g1[cA + 0], accA.x);
        atomicAdd(&g_g1[cA + 1], accA.y);
        atomicAdd(&g_g1[cA + 2], accA.z);
        atomicAdd(&g_g1[cA + 3], accA.w);
        atomicAdd(&g_g1[cB + 0], accB.x);
        atomicAdd(&g_g1[cB + 1], accB.y);
        atomicAdd(&g_g1[cB + 2], accB.z);
        atomicAdd(&g_g1[cB + 3], accB.w);
    } else {
        const int rowBase = (blockIdx.x - 128) * 32;
        const float4* xv = (const float4*)g_x2;
        float4 xC[4];
        #pragma unroll
        for (int k = 0; k < 4; k++) xC[k] = xv[tid + k * 512];
        float4 acc[4] = {make_float4(0,0,0,0), make_float4(0,0,0,0),
                         make_float4(0,0,0,0), make_float4(0,0,0,0)};

        #pragma unroll 1
        for (int t = 0; t < 8; t++) {
            const int rb = rowBase + t * 4;
            const float4* base = (const float4*)W1 + (size_t)rb * 2048 + tid;
            float4 w[4][4];
            #pragma unroll
            for (int r = 0; r < 4; r++)
                #pragma unroll
                for (int k = 0; k < 4; k++)
                    w[r][k] = base[(size_t)r * 2048 + k * 512];
            #pragma unroll
            for (int r = 0; r < 4; r++) {
                uint2* dst = (uint2*)g_W1h + (size_t)(rb + r) * 2048;
                #pragma unroll
                for (int k = 0; k < 4; k++)
                    dst[tid + k * 512] = f4_to_h4(w[r][k]);
            }
            #pragma unroll
            for (int r = 0; r < 4; r++) {
                float p = dot4(w[r][0], xC[0]) + dot4(w[r][1], xC[1])
                        + dot4(w[r][2], xC[2]) + dot4(w[r][3], xC[3]);
                #pragma unroll
                for (int o = 16; o; o >>= 1) p += __shfl_xor_sync(0xFFFFFFFFu, p, o);
                if (lane == 0) sp[r][warp] = p;
            }
            __syncthreads();
            if (tid < 4) {
                float s = 0.f;
                #pragma unroll
                for (int wi = 0; wi < 16; wi++) s += sp[tid][wi];
                float e = g_x1[rb + tid] - tanhf(s);
                se[tid] = e;
                g_e1[rb + tid] = e;
            }
            __syncthreads();
            #pragma unroll
            for (int r = 0; r < 4; r++) {
                const float e = se[r];
                #pragma unroll
                for (int k = 0; k < 4; k++) {
                    acc[k].x += e * w[r][k].x;  acc[k].y += e * w[r][k].y;
                    acc[k].z += e * w[r][k].z;  acc[k].w += e * w[r][k].w;
                }
            }
        }
        #pragma unroll
        for (int k = 0; k < 4; k++) {
            const int c = 4 * (tid + k * 512);
            atomicAdd(&g_g2[c + 0], acc[k].x);
            atomicAdd(&g_g2[c + 1], acc[k].y);
            atomicAdd(&g_g2[c + 2], acc[k].z);
            atomicAdd(&g_g2[c + 3], acc[k].w);
        }
    }
    step_epilogue(256);
}

// ---------------------------------------------------------------------------
// Steps 2..9: fp16 fused step, 512 threads, register-budgeted (NO spills):
//   W0 branch: thread owns 1 uint4 (8 halfs)/row, 16-row tiles (w: 64 regs,
//              accf: 8, xf: 8)
//   W1 branch: thread owns 2 uint4/row, 8-row tiles (w: 64 regs, accf: 16)
// Blocks [0,128): W0 (64 rows). Blocks [128,256): W1 (32 rows).
// ---------------------------------------------------------------------------
__global__ void __launch_bounds__(512) k_step_h(const float* __restrict__ x0) {
    __shared__ float sp[16][16];
    __shared__ float se[16];
    const int tid  = threadIdx.x;
    const int warp = tid >> 5;
    const int lane = tid & 31;

    if (blockIdx.x < 128) {
        // ------------- W0h: [8192 x 4096] halfs, row = 512 uint4 -----------
        const int rowBase = blockIdx.x * 64;
        const uint4* W = (const uint4*)g_W0h;
        float xf[8];
        {
            const float4* xv = (const float4*)g_x1;
            float4 a = xv[2 * tid], b = xv[2 * tid + 1];
            xf[0]=a.x; xf[1]=a.y; xf[2]=a.z; xf[3]=a.w;
            xf[4]=b.x; xf[5]=b.y; xf[6]=b.z; xf[7]=b.w;
        }
        float accf[8];
        #pragma unroll
        for (int j = 0; j < 8; j++) accf[j] = 0.f;

        #pragma unroll 1
        for (int t = 0; t < 4; t++) {
            const int rb = rowBase + t * 16;
            const uint4* base = W + (size_t)rb * 512 + tid;
            uint4 w[16];
            #pragma unroll
            for (int r = 0; r < 16; r++) w[r] = base[(size_t)r * 512];

            #pragma unroll
            for (int r = 0; r < 16; r++) {
                float wf[8];
                h8_to_f8(w[r], wf);
                float p = wf[0]*xf[0] + wf[1]*xf[1] + wf[2]*xf[2] + wf[3]*xf[3]
                        + wf[4]*xf[4] + wf[5]*xf[5] + wf[6]*xf[6] + wf[7]*xf[7];
                #pragma unroll
                for (int o = 16; o; o >>= 1) p += __shfl_xor_sync(0xFFFFFFFFu, p, o);
                if (lane == 0) sp[r][warp] = p;
            }
            __syncthreads();
            // combine: warp r reduces row r across 16 warps
            if (lane < 16) {
                float v = sp[warp][lane];
                v += __shfl_xor_sync(0x0000FFFFu, v, 8);
                v += __shfl_xor_sync(0x0000FFFFu, v, 4);
                v += __shfl_xor_sync(0x0000FFFFu, v, 2);
                v += __shfl_xor_sync(0x0000FFFFu, v, 1);
                if (lane == 0) se[warp] = x0[rb + warp] - tanhf(v);
            }
            __syncthreads();
            #pragma unroll
            for (int r = 0; r < 16; r++) {
                const float e = se[r];
                float wf[8];
                h8_to_f8(w[r], wf);
                #pragma unroll
                for (int j = 0; j < 8; j++) accf[j] += e * wf[j];
            }
            __syncthreads();
        }
        #pragma unroll
        for (int j = 0; j < 8; j++) atomicAdd(&g_g1[8 * tid + j], accf[j]);
    } else {
        // ------------- W1h: [4096 x 8192] halfs, row = 1024 uint4 ----------
        const int rowBase = (blockIdx.x - 128) * 32;
        const uint4* W = (const uint4*)g_W1h;
        float xfA[8], xfB[8];
        {
            const float4* xv = (const float4*)g_x2;
            float4 a = xv[2 * tid],           b = xv[2 * tid + 1];
            float4 c = xv[2 * (tid + 512)],   d = xv[2 * (tid + 512) + 1];
            xfA[0]=a.x; xfA[1]=a.y; xfA[2]=a.z; xfA[3]=a.w;
            xfA[4]=b.x; xfA[5]=b.y; xfA[6]=b.z; xfA[7]=b.w;
            xfB[0]=c.x; xfB[1]=c.y; xfB[2]=c.z; xfB[3]=c.w;
            xfB[4]=d.x; xfB[5]=d.y; xfB[6]=d.z; xfB[7]=d.w;
        }
        float accA[8], accB[8];
        #pragma unroll
        for (int j = 0; j < 8; j++) { accA[j] = 0.f; accB[j] = 0.f; }

        #pragma unroll 1
        for (int t = 0; t < 4; t++) {
            const int rb = rowBase + t * 8;
            const uint4* base = W + (size_t)rb * 1024 + tid;
            uint4 wA[8], wB[8];
            #pragma unroll
            for (int r = 0; r < 8; r++) {
                wA[r] = base[(size_t)r * 1024];
                wB[r] = base[(size_t)r * 1024 + 512];
            }
            #pragma unroll
            for (int r = 0; r < 8; r++) {
                float wf[8];
                h8_to_f8(wA[r], wf);
                float p = wf[0]*xfA[0] + wf[1]*xfA[1] + wf[2]*xfA[2] + wf[3]*xfA[3]
                        + wf[4]*xfA[4] + wf[5]*xfA[5] + wf[6]*xfA[6] + wf[7]*xfA[7];
                h8_to_f8(wB[r], wf);
                p += wf[0]*xfB[0] + wf[1]*xfB[1] + wf[2]*xfB[2] + wf[3]*xfB[3]
                   + wf[4]*xfB[4] + wf[5]*xfB[5] + wf[6]*xfB[6] + wf[7]*xfB[7];
                #pragma unroll
                for (int o = 16; o; o >>= 1) p += __shfl_xor_sync(0xFFFFFFFFu, p, o);
                if (lane == 0) sp[r][warp] = p;
            }
            __syncthreads();
            if (warp < 8 && lane < 16) {
                float v = sp[warp][lane];
                v += __shfl_xor_sync(0x0000FFFFu, v, 8);
                v += __shfl_xor_sync(0x0000FFFFu, v, 4);
                v += __shfl_xor_sync(0x0000FFFFu, v, 2);
                v += __shfl_xor_sync(0x0000FFFFu, v, 1);
                if (lane == 0) {
                    float e = g_x1[rb + warp] - tanhf(v);
                    se[warp] = e;
                    g_e1[rb + warp] = e;
                }
            }
            __syncthreads();
            #pragma unroll
            for (int r = 0; r < 8; r++) {
                const float e = se[r];
                float wf[8];
                h8_to_f8(wA[r], wf);
                #pragma unroll
                for (int j = 0; j < 8; j++) accA[j] += e * wf[j];
                h8_to_f8(wB[r], wf);
                #pragma unroll
                for (int j = 0; j < 8; j++) accB[j] += e * wf[j];
            }
            __syncthreads();
        }
        #pragma unroll
        for (int j = 0; j < 8; j++) atomicAdd(&g_g2[8 * tid + j], accA[j]);
        #pragma unroll
        for (int j = 0; j < 8; j++) atomicAdd(&g_g2[8 * (tid + 512) + j], accB[j]);
    }
    step_epilogue(256);
}

// ---------------------------------------------------------------------------
// Final: err = ||x0 - tanh(W0@x1)||^2 + ||x1 - tanh(W1@x2)||^2 + ||x2||^2
// fp16 weights, warp-per-row.
// ---------------------------------------------------------------------------
__global__ void __launch_bounds__(256) k_final_h(const float* __restrict__ x0,
                                                 float* __restrict__ out) {
    __shared__ float s_part[8];
    const int warpInBlock = threadIdx.x >> 5;
    const int warp = (blockIdx.x * blockDim.x + threadIdx.x) >> 5;
    const int lane = threadIdx.x & 31;

    float local = 0.f;
    if (warp < N0) {
        const uint4* row = (const uint4*)g_W0h + (size_t)warp * 512;
        const float4* xv = (const float4*)g_x1;
        float acc = 0.f;
        #pragma unroll 4
        for (int i = lane; i < 512; i += 32) {
            uint4 w = row[i];
            float wf[8];
            h8_to_f8(w, wf);
            float4 a = xv[2 * i], b = xv[2 * i + 1];
            acc += wf[0]*a.x + wf[1]*a.y + wf[2]*a.z + wf[3]*a.w
                 + wf[4]*b.x + wf[5]*b.y + wf[6]*b.z + wf[7]*b.w;
        }
        #pragma unroll
        for (int o = 16; o; o >>= 1) acc += __shfl_xor_sync(0xFFFFFFFFu, acc, o);
        if (lane == 0) {
            float e = x0[warp] - tanhf(acc);
            float x2v = g_x2[warp];
            local = e * e + x2v * x2v;
        }
    } else {
        const int r = warp - N0;
        const uint4* row = (const uint4*)g_W1h + (size_t)r * 1024;
        const float4* xv = (const float4*)g_x2;
        float acc = 0.f;
        #pragma unroll 4
        for (int i = lane; i < 1024; i += 32) {
            uint4 w = row[i];
            float wf[8];
            h8_to_f8(w, wf);
            float4 a = xv[2 * i], b = xv[2 * i + 1];
            acc += wf[0]*a.x + wf[1]*a.y + wf[2]*a.z + wf[3]*a.w
                 + wf[4]*b.x + wf[5]*b.y + wf[6]*b.z + wf[7]*b.w;
        }
        #pragma unroll
        for (int o = 16; o; o >>= 1) acc += __shfl_xor_sync(0xFFFFFFFFu, acc, o);
        if (lane == 0) {
            float e = g_x1[r] - tanhf(acc);
            local = e * e;
        }
    }

    if (lane == 0) s_part[warpInBlock] = local;
    __syncthreads();
    if (threadIdx.x == 0) {
        float s = 0.f;
        #pragma unroll
        for (int w = 0; w < 8; w++) s += s_part[w];
        atomicAdd(out, s);
    }
}

// ---------------------------------------------------------------------------
extern "C" void kernel_launch(void* const* d_in, const int* in_sizes, int n_in,
                              void* d_out, int out_size) {
    const float* x0 = (const float*)d_in[0];
    const float* W0 = (const float*)d_in[1];
    const float* W1 = (const float*)d_in[2];
    float* out = (float*)d_out;

    k_init<<<32, 256>>>(out);
    k_step1<<<256, 512>>>(x0, W0, W1);          // fp32 step + fp16 conversion
    for (int s = 0; s < 8; s++)
        k_step_h<<<256, 512>>>(x0);             // fp16 steps 2..9
    k_final_h<<<(N0 + N1) / 8, 256>>>(x0, out); // fp16 final error
}